// round 11
// baseline (speedup 1.0000x reference)
#include <cuda_runtime.h>
#include <cstdint>
#include <cstddef>

// Problem constants
#define BB 32
#define TT 256
#define DD 512
#define HH 1024
#define GN 4096          // 4*H gate columns
#define MM (BB*TT)       // 8192 rows

#define NBLK 128         // persistent blocks (1/SM, all co-resident)
#define UPB 8            // hidden units per block (x4 gates = 32 cols)
#define PTH 256          // threads in persistent kernel (8 warps, 2/SMSP)

// ---------------- scratch (static device allocations; no cudaMalloc) -------
__device__ float g_zx[(size_t)MM * GN];      // input-projection Z (128 MB)
__device__ float g_h1[(size_t)MM * HH];      // layer-1 hidden history (32 MB)
__device__ float g_hT[2][HH * BB];           // transposed h double buffer [unit][batch]
__device__ unsigned g_bar_grp[8 * 64];       // 8 group counters, 256B apart
__device__ unsigned g_bar_root;
__device__ unsigned g_bar_phase;

// ---------------- f32x2 packed FMA (Blackwell FFMA2) -----------------------
__device__ __forceinline__ float2 ffma2(float2 a, float2 b, float2 c) {
    unsigned long long au = *reinterpret_cast<unsigned long long*>(&a);
    unsigned long long bu = *reinterpret_cast<unsigned long long*>(&b);
    unsigned long long cu = *reinterpret_cast<unsigned long long*>(&c);
    unsigned long long du;
    asm("fma.rn.f32x2 %0, %1, %2, %3;" : "=l"(du) : "l"(au), "l"(bu), "l"(cu));
    return *reinterpret_cast<float2*>(&du);
}

// ---------------- cp.async helpers ------------------------------------------
__device__ __forceinline__ void cp_async16(uint32_t dst_smem, const void* src) {
    asm volatile("cp.async.cg.shared.global [%0], [%1], 16;" :: "r"(dst_smem), "l"(src));
}
__device__ __forceinline__ void cp_commit() {
    asm volatile("cp.async.commit_group;" ::: "memory");
}
template <int N>
__device__ __forceinline__ void cp_wait() {
    asm volatile("cp.async.wait_group %0;" :: "n"(N) : "memory");
}

// ---------------- tf32 helpers ----------------------------------------------
__device__ __forceinline__ uint32_t f2tf32(float x) {
    uint32_t r; asm("cvt.rna.tf32.f32 %0, %1;" : "=r"(r) : "f"(x)); return r;
}
__device__ __forceinline__ void mma8(float* c, uint32_t a0, uint32_t a1,
                                     uint32_t a2, uint32_t a3,
                                     uint32_t b0, uint32_t b1) {
    asm volatile("mma.sync.aligned.m16n8k8.row.col.f32.tf32.tf32.f32 "
        "{%0,%1,%2,%3}, {%4,%5,%6,%7}, {%8,%9}, {%0,%1,%2,%3};"
        : "+f"(c[0]), "+f"(c[1]), "+f"(c[2]), "+f"(c[3])
        : "r"(a0), "r"(a1), "r"(a2), "r"(a3), "r"(b0), "r"(b1));
}

// ---------------- 3xTF32 GEMM: C[M,N] = A[M,K] * B[K,N] --------------------
// 128x128x16 block tile, 256 threads = 8 warps (4x2), warp tile 32x64.
// smem layout per element: float4 groups [big(sig0), sml(sig0), big(sig1),
// sml(sig1)] where sig0 = true-k tg, sig1 = tg+4 within each k8 slice, so a
// single LDS.128 yields the (a0,a2)/(a1,a3) or (b0,b1) pair for BOTH big and
// small fragments. 3 mma per tile pair (bb, bs, sb) -> fp32-level accuracy.
__global__ __launch_bounds__(256) void sgemm_tf32(
    const float* __restrict__ A, const float* __restrict__ B,
    float* __restrict__ C, int M, int N, int K)
{
    __shared__ float4 A_s[128 * 9];   // row*9 + ks8*4 + tg  (slot 8 = pad)
    __shared__ float4 B_s[128 * 9];   // col*9 + ks8*4 + tg

    const int tid = threadIdx.x;
    const int m0 = blockIdx.y * 128;
    const int n0 = blockIdx.x * 128;
    const int wid = tid >> 5;
    const int lane = tid & 31;
    const int g = lane >> 2;          // 0..7
    const int tg = lane & 3;          // 0..3
    const int wm = wid >> 1;          // 0..3 -> 32 rows
    const int wn = wid & 1;           // 0..1 -> 64 cols

    float acc[2][8][4];
#pragma unroll
    for (int mt = 0; mt < 2; ++mt)
#pragma unroll
        for (int nt = 0; nt < 8; ++nt)
#pragma unroll
            for (int e = 0; e < 4; ++e) acc[mt][nt][e] = 0.f;

    // per-thread global-load geometry
    const int a_row = tid >> 2;            // 0..63 (+64 second half)
    const int a_kq = (tid & 3) << 2;       // 0,4,8,12
    const int b_kr = tid >> 5;             // 0..7 (+8)
    const int b_nq = (tid & 31) << 2;

    float4 va[2], vb[2];
    // prefetch tile k0=0
    va[0] = *(const float4*)(A + (size_t)(m0 + a_row) * K + a_kq);
    va[1] = *(const float4*)(A + (size_t)(m0 + a_row + 64) * K + a_kq);
    vb[0] = *(const float4*)(B + (size_t)b_kr * N + n0 + b_nq);
    vb[1] = *(const float4*)(B + (size_t)(b_kr + 8) * N + n0 + b_nq);

    for (int k0 = 0; k0 < K; k0 += 16) {
        // ---- store prefetched tile to smem with big/small split ----
        {
            int ks8 = a_kq >> 3;
            int half = (a_kq >> 2) & 1;
#pragma unroll
            for (int l = 0; l < 2; ++l) {
                int row = a_row + l * 64;
                float vv[4] = {va[l].x, va[l].y, va[l].z, va[l].w};
#pragma unroll
                for (int e = 0; e < 4; ++e) {
                    uint32_t big = f2tf32(vv[e]);
                    float bf = __uint_as_float(big);
                    uint32_t sml = f2tf32(vv[e] - bf);
                    float2* dst = (float2*)&A_s[row * 9 + ks8 * 4 + e];
                    dst[half] = make_float2(__uint_as_float(big), __uint_as_float(sml));
                }
            }
#pragma unroll
            for (int l = 0; l < 2; ++l) {
                int kr = b_kr + l * 8;
                int bks8 = kr >> 3;
                int kk = kr & 7;
                int btg = kk & 3;
                int bhalf = kk >> 2;
                float vv[4] = {vb[l].x, vb[l].y, vb[l].z, vb[l].w};
#pragma unroll
                for (int e = 0; e < 4; ++e) {
                    uint32_t big = f2tf32(vv[e]);
                    float bf = __uint_as_float(big);
                    uint32_t sml = f2tf32(vv[e] - bf);
                    float2* dst = (float2*)&B_s[(b_nq + e) * 9 + bks8 * 4 + btg];
                    dst[bhalf] = make_float2(__uint_as_float(big), __uint_as_float(sml));
                }
            }
        }
        __syncthreads();

        // prefetch next tile (consumed at next iteration's store phase)
        if (k0 + 16 < K) {
            va[0] = *(const float4*)(A + (size_t)(m0 + a_row) * K + k0 + 16 + a_kq);
            va[1] = *(const float4*)(A + (size_t)(m0 + a_row + 64) * K + k0 + 16 + a_kq);
            vb[0] = *(const float4*)(B + (size_t)(k0 + 16 + b_kr) * N + n0 + b_nq);
            vb[1] = *(const float4*)(B + (size_t)(k0 + 16 + b_kr + 8) * N + n0 + b_nq);
        }

        // ---- compute: 2 k8 slices ----
#pragma unroll
        for (int ks = 0; ks < 2; ++ks) {
            float4 p[2], q[2];
#pragma unroll
            for (int mt = 0; mt < 2; ++mt) {
                int rb = wm * 32 + mt * 16;
                p[mt] = A_s[(rb + g) * 9 + ks * 4 + tg];
                q[mt] = A_s[(rb + 8 + g) * 9 + ks * 4 + tg];
            }
            float4 r[8];
#pragma unroll
            for (int nt = 0; nt < 8; ++nt)
                r[nt] = B_s[(wn * 64 + nt * 8 + g) * 9 + ks * 4 + tg];

#pragma unroll
            for (int mt = 0; mt < 2; ++mt) {
                uint32_t ab0 = __float_as_uint(p[mt].x), ab1 = __float_as_uint(q[mt].x);
                uint32_t ab2 = __float_as_uint(p[mt].z), ab3 = __float_as_uint(q[mt].z);
                uint32_t as0 = __float_as_uint(p[mt].y), as1 = __float_as_uint(q[mt].y);
                uint32_t as2 = __float_as_uint(p[mt].w), as3 = __float_as_uint(q[mt].w);
#pragma unroll
                for (int nt = 0; nt < 8; ++nt) {
                    uint32_t bb0 = __float_as_uint(r[nt].x), bb1 = __float_as_uint(r[nt].z);
                    uint32_t bs0 = __float_as_uint(r[nt].y), bs1 = __float_as_uint(r[nt].w);
                    float* c = acc[mt][nt];
                    mma8(c, ab0, ab1, ab2, ab3, bb0, bb1);   // big x big
                    mma8(c, ab0, ab1, ab2, ab3, bs0, bs1);   // big x small
                    mma8(c, as0, as1, as2, as3, bb0, bb1);   // small x big
                }
            }
        }
        __syncthreads();
    }

    // ---- epilogue ----
#pragma unroll
    for (int mt = 0; mt < 2; ++mt) {
#pragma unroll
        for (int nt = 0; nt < 8; ++nt) {
            int row = m0 + wm * 32 + mt * 16 + g;
            int col = n0 + wn * 64 + nt * 8 + tg * 2;
            float* c = acc[mt][nt];
            *(float2*)(C + (size_t)row * N + col) = make_float2(c[0], c[1]);
            *(float2*)(C + (size_t)(row + 8) * N + col) = make_float2(c[2], c[3]);
        }
    }
}

// ---------------- reset: barrier counters + h state ------------------------
__global__ void reset_kernel() {
    int i = blockIdx.x * blockDim.x + threadIdx.x;
    if (i < 8 * 64) g_bar_grp[i] = 0u;
    if (i == 0) { g_bar_root = 0u; g_bar_phase = 0u; }
    if (i < 2 * HH * BB) ((float*)g_hT)[i] = 0.f;
}

// ---------------- persistent LSTM layer kernel (round-10 core) -------------
// 128 blocks x 256 threads; thread (cq,bq,kq) = 4 cols x 4 batches x K/4.
// Grid barrier: 2-level tree (8 group counters -> root -> phase release).
__global__ __launch_bounds__(PTH, 1) void lstm_persistent(
    const float* __restrict__ Wh,       // [HH][GN] recurrent weights
    const float* __restrict__ zx,       // [MM][GN], row = b*TT + t
    const float* __restrict__ bias,     // [GN]
    float* __restrict__ hist)           // [MM][HH] h history out
{
    extern __shared__ float smem[];
    float* w_s = smem;                           // [k*32 + col], 32768 floats
    float* h_s = smem + 32768;                   // 2 x 4096 floats
    float* z_s = smem + 32768 + 2 * 4096;        // 4 x (32*36)

    const int tid = threadIdx.x;
    const int bx = blockIdx.x;
    const int u0 = bx * UPB;
    const int cq = tid & 7;              // col quad: cols {4cq..4cq+3}
    const int bq = (tid >> 3) & 7;       // batch quad
    const int kq = tid >> 6;             // K quarter 0..3 (uniform per warp)
    const int gu = tid & 7;              // gate-phase unit
    const int gb = tid >> 3;             // gate-phase batch 0..31

    float* hT = (float*)g_hT;

    // ---- load weight slice into smem: w_s[k*32 + cc] ----
#pragma unroll 8
    for (int l = 0; l < 128; ++l) {
        int i = tid + l * PTH;           // 0..32767
        int k = i >> 5;
        int cc = i & 31;
        int col = ((cc >> 3) << 10) + u0 + (cc & 7);
        w_s[i] = Wh[(size_t)k * GN + col];
    }

    float bi = bias[0 * HH + u0 + gu];
    float bj = bias[1 * HH + u0 + gu];
    float bf = bias[2 * HH + u0 + gu];
    float bo = bias[3 * HH + u0 + gu];

    float creg = 0.f;
    __syncthreads();

    // per-thread chunk-load geometry: 4 float4s/thread/chunk
    const int ld_row = tid >> 3;          // base row 0..31 (stride 32)
    const int ld_c4 = (tid & 7) << 2;     // 0,4,..28

    for (int t = 0; t < TT; ++t) {
        const float* hread = hT + (t & 1) * (HH * BB);
        float* hwrite = hT + ((t + 1) & 1) * (HH * BB);

        // prefetch this step's zx for the gate phase
        const float* zxr = zx + (size_t)(gb * TT + t) * GN + u0 + gu;
        float zxi = __ldg(zxr);
        float zxj = __ldg(zxr + HH);
        float zxf = __ldg(zxr + 2 * HH);
        float zxo = __ldg(zxr + 3 * HH);

        // preload chunk 0 into buffer 0
        {
            uint32_t dst = (uint32_t)__cvta_generic_to_shared(h_s);
#pragma unroll
            for (int l = 0; l < 4; ++l) {
                int row = ld_row + l * 32;
                cp_async16(dst + (row * 32 + ld_c4) * 4,
                           hread + row * BB + ld_c4);
            }
            cp_commit();
        }

        float2 alo[4], ahi[4];
#pragma unroll
        for (int c = 0; c < 4; ++c) {
            alo[c] = make_float2(0.f, 0.f);
            ahi[c] = make_float2(0.f, 0.f);
        }

#pragma unroll 1
        for (int ch = 0; ch < 8; ++ch) {
            if (ch < 7) {   // prefetch next chunk into other buffer
                float* hb_next = h_s + ((ch + 1) & 1) * 4096;
                uint32_t dst = (uint32_t)__cvta_generic_to_shared(hb_next);
                const float* src = hread + (ch + 1) * 128 * BB;
#pragma unroll
                for (int l = 0; l < 4; ++l) {
                    int row = ld_row + l * 32;
                    cp_async16(dst + (row * 32 + ld_c4) * 4,
                               src + row * BB + ld_c4);
                }
                cp_commit();
                cp_wait<1>();
            } else {
                cp_wait<0>();
            }
            __syncthreads();   // chunk ch visible to all warps

            const float* hb = h_s + (ch & 1) * 4096 + (kq * 32) * 32 + bq * 4;
            const float* wb = w_s + (ch * 128 + kq * 32) * 32 + cq * 4;
#pragma unroll 8
            for (int kk = 0; kk < 32; ++kk) {
                float4 wv = *(const float4*)(wb + kk * 32);
                float4 hv = *(const float4*)(hb + kk * 32);
                float2 hlo = make_float2(hv.x, hv.y);
                float2 hhi = make_float2(hv.z, hv.w);
                alo[0] = ffma2(hlo, make_float2(wv.x, wv.x), alo[0]);
                ahi[0] = ffma2(hhi, make_float2(wv.x, wv.x), ahi[0]);
                alo[1] = ffma2(hlo, make_float2(wv.y, wv.y), alo[1]);
                ahi[1] = ffma2(hhi, make_float2(wv.y, wv.y), ahi[1]);
                alo[2] = ffma2(hlo, make_float2(wv.z, wv.z), alo[2]);
                ahi[2] = ffma2(hhi, make_float2(wv.z, wv.z), ahi[2]);
                alo[3] = ffma2(hlo, make_float2(wv.w, wv.w), alo[3]);
                ahi[3] = ffma2(hhi, make_float2(wv.w, wv.w), ahi[3]);
            }
            __syncthreads();   // free buffer (ch&1) for chunk ch+2 prefetch
        }

        // stage K-quarter partials to smem
        float* zh = z_s + kq * (32 * 36);
#pragma unroll
        for (int c = 0; c < 4; ++c) {
            *(float4*)(zh + (cq * 4 + c) * 36 + bq * 4) =
                make_float4(alo[c].x, alo[c].y, ahi[c].x, ahi[c].y);
        }
        __syncthreads();

        // ---- gate phase: thread = (unit gu, batch gb), combine 4 quarters --
        {
            float zi = zxi + bi, zj = zxj + bj, zf = zxf + bf, zo = zxo + bo;
#pragma unroll
            for (int q = 0; q < 4; ++q) {
                const float* zq = z_s + q * (32 * 36);
                zi += zq[(0 * 8 + gu) * 36 + gb];
                zj += zq[(1 * 8 + gu) * 36 + gb];
                zf += zq[(2 * 8 + gu) * 36 + gb];
                zo += zq[(3 * 8 + gu) * 36 + gb];
            }

            float ig = 1.f / (1.f + expf(-zi));
            float fg = 1.f / (1.f + expf(-(zf + 1.0f)));   // forget bias 1.0
            float jt = tanhf(zj);
            float cn = fg * creg + ig * jt;
            float og = 1.f / (1.f + expf(-zo));
            float hn = og * tanhf(cn);
            creg = cn;

            hwrite[(u0 + gu) * BB + gb] = hn;
            hist[(size_t)(gb * TT + t) * HH + u0 + gu] = hn;
        }

        // ---- 2-level tree grid barrier, single poller per block ----
        if (t < TT - 1) {
            __syncthreads();   // block's h writes issued (also z_s guard)
            unsigned target = (unsigned)(t + 1);
            if (tid == 0) {
                unsigned* gaddr = g_bar_grp + ((bx >> 4) << 6);
                unsigned prev;
                asm volatile("atom.add.release.gpu.global.u32 %0, [%1], 1;"
                             : "=r"(prev) : "l"(gaddr) : "memory");
                bool released = false;
                if (prev == 15u) {
                    *gaddr = 0u;   // ordered by release-RMW chain below
                    unsigned pr;
                    asm volatile("atom.add.release.gpu.global.u32 %0, [%1], 1;"
                                 : "=r"(pr) : "l"(&g_bar_root) : "memory");
                    if (pr == 7u) {
                        g_bar_root = 0u;   // ordered by st.release below
                        asm volatile("st.release.gpu.global.u32 [%0], %1;"
                                     :: "l"(&g_bar_phase), "r"(target) : "memory");
                        released = true;
                    }
                }
                if (!released) {
                    unsigned ph;
                    do {
                        asm volatile("ld.acquire.gpu.global.u32 %0, [%1];"
                                     : "=r"(ph) : "l"(&g_bar_phase) : "memory");
                        if (ph >= target) break;
                        __nanosleep(64);
                    } while (true);
                }
            }
            __syncthreads();
        } else {
            __syncthreads();
        }
    }
}

// ---------------- host orchestration ---------------------------------------
extern "C" void kernel_launch(void* const* d_in, const int* in_sizes, int n_in,
                              void* d_out, int out_size)
{
    const float *x = nullptr, *W1 = nullptr, *b1 = nullptr, *W2 = nullptr, *b2 = nullptr;
    for (int i = 0; i < n_in; i++) {
        int s = in_sizes[i];
        const float* p = (const float*)d_in[i];
        if (s == BB * TT * DD) x = p;
        else if (s == (DD + HH) * GN) W1 = p;
        else if (s == (HH + HH) * GN) W2 = p;
        else if (s == GN) { if (!b1) b1 = p; else b2 = p; }
    }
    float* out = (float*)d_out;

    float *zx, *h1;
    { void* p; cudaGetSymbolAddress(&p, g_zx); zx = (float*)p; }
    { void* p; cudaGetSymbolAddress(&p, g_h1); h1 = (float*)p; }

    const int SMEM_BYTES = (32768 + 2 * 4096 + 4 * 32 * 36) * 4;   // ~182 KB
    cudaFuncSetAttribute(lstm_persistent,
                         cudaFuncAttributeMaxDynamicSharedMemorySize, SMEM_BYTES);

    dim3 gemm_grid(GN / 128, MM / 128);   // (32, 64)

    // ---- Layer 1 ----
    sgemm_tf32<<<gemm_grid, 256>>>(x, W1, zx, MM, GN, DD);
    reset_kernel<<<(2 * HH * BB + 255) / 256, 256>>>();
    lstm_persistent<<<NBLK, PTH, SMEM_BYTES>>>(W1 + (size_t)DD * GN, zx, b1, h1);

    // ---- Layer 2 ----
    sgemm_tf32<<<gemm_grid, 256>>>(h1, W2, zx, MM, GN, HH);
    reset_kernel<<<(2 * HH * BB + 255) / 256, 256>>>();
    lstm_persistent<<<NBLK, PTH, SMEM_BYTES>>>(W2 + (size_t)HH * GN, zx, b2, out);
}

// round 12
// speedup vs baseline: 1.0428x; 1.0428x over previous
#include <cuda_runtime.h>
#include <cstdint>
#include <cstddef>

// Problem constants
#define BB 32
#define TT 256
#define DD 512
#define HH 1024
#define GN 4096          // 4*H gate columns
#define MM (BB*TT)       // 8192 rows

#define NBLK 128         // persistent blocks (1/SM, all co-resident)
#define UPB 8            // hidden units per block (x4 gates = 32 cols)
#define PTH 256          // threads in persistent kernel (8 warps, 2/SMSP)

// ---------------- scratch (static device allocations; no cudaMalloc) -------
__device__ float g_zx[(size_t)MM * GN];      // input-projection Z (128 MB)
__device__ float g_h1[(size_t)MM * HH];      // layer-1 hidden history (32 MB)
__device__ float g_hT[2][HH * BB];           // transposed h double buffer [unit][batch]
__device__ unsigned g_bar_count;
__device__ unsigned g_bar_phase;

// ---------------- f32x2 packed FMA (Blackwell FFMA2) -----------------------
__device__ __forceinline__ float2 ffma2(float2 a, float2 b, float2 c) {
    unsigned long long au = *reinterpret_cast<unsigned long long*>(&a);
    unsigned long long bu = *reinterpret_cast<unsigned long long*>(&b);
    unsigned long long cu = *reinterpret_cast<unsigned long long*>(&c);
    unsigned long long du;
    asm("fma.rn.f32x2 %0, %1, %2, %3;" : "=l"(du) : "l"(au), "l"(bu), "l"(cu));
    return *reinterpret_cast<float2*>(&du);
}

// ---------------- cp.async helpers ------------------------------------------
__device__ __forceinline__ void cp_async16(uint32_t dst_smem, const void* src) {
    asm volatile("cp.async.cg.shared.global [%0], [%1], 16;" :: "r"(dst_smem), "l"(src));
}
__device__ __forceinline__ void cp_commit() {
    asm volatile("cp.async.commit_group;" ::: "memory");
}
template <int N>
__device__ __forceinline__ void cp_wait() {
    asm volatile("cp.async.wait_group %0;" :: "n"(N) : "memory");
}

// ---------------- tf32 helpers ----------------------------------------------
__device__ __forceinline__ uint32_t f2tf32(float x) {
    uint32_t r; asm("cvt.rna.tf32.f32 %0, %1;" : "=r"(r) : "f"(x)); return r;
}
__device__ __forceinline__ void mma8(float* c, uint32_t a0, uint32_t a1,
                                     uint32_t a2, uint32_t a3,
                                     uint32_t b0, uint32_t b1) {
    asm volatile("mma.sync.aligned.m16n8k8.row.col.f32.tf32.tf32.f32 "
        "{%0,%1,%2,%3}, {%4,%5,%6,%7}, {%8,%9}, {%0,%1,%2,%3};"
        : "+f"(c[0]), "+f"(c[1]), "+f"(c[2]), "+f"(c[3])
        : "r"(a0), "r"(a1), "r"(a2), "r"(a3), "r"(b0), "r"(b1));
}

// ---------------- 3xTF32 GEMM: C[M,N] = A[M,K] * B[K,N] --------------------
// 128x128x16 block tile, 256 threads = 8 warps (4x2), warp tile 32x64.
// smem per element: float4 [big(sig0), sml(sig0), big(sig1), sml(sig1)] so a
// single LDS.128 yields big+small fragment pairs. 3 mma per pair (bb,bs,sb).
// launch_bounds(256,2): 2 CTAs/SM; B-fragments processed in 2 chunks of 4 to
// keep regs <= 128 (no hot-loop spills).
__global__ __launch_bounds__(256, 2) void sgemm_tf32(
    const float* __restrict__ A, const float* __restrict__ B,
    float* __restrict__ C, int M, int N, int K)
{
    __shared__ float4 A_s[128 * 9];   // row*9 + ks8*4 + tg  (slot 8 = pad)
    __shared__ float4 B_s[128 * 9];   // col*9 + ks8*4 + tg

    const int tid = threadIdx.x;
    const int m0 = blockIdx.y * 128;
    const int n0 = blockIdx.x * 128;
    const int wid = tid >> 5;
    const int lane = tid & 31;
    const int g = lane >> 2;          // 0..7
    const int tg = lane & 3;          // 0..3
    const int wm = wid >> 1;          // 0..3 -> 32 rows
    const int wn = wid & 1;           // 0..1 -> 64 cols

    float acc[2][8][4];
#pragma unroll
    for (int mt = 0; mt < 2; ++mt)
#pragma unroll
        for (int nt = 0; nt < 8; ++nt)
#pragma unroll
            for (int e = 0; e < 4; ++e) acc[mt][nt][e] = 0.f;

    // per-thread global-load geometry
    const int a_row = tid >> 2;            // 0..63 (+64 second half)
    const int a_kq = (tid & 3) << 2;       // 0,4,8,12
    const int b_kr = tid >> 5;             // 0..7 (+8)
    const int b_nq = (tid & 31) << 2;

    float4 va[2], vb[2];
    va[0] = *(const float4*)(A + (size_t)(m0 + a_row) * K + a_kq);
    va[1] = *(const float4*)(A + (size_t)(m0 + a_row + 64) * K + a_kq);
    vb[0] = *(const float4*)(B + (size_t)b_kr * N + n0 + b_nq);
    vb[1] = *(const float4*)(B + (size_t)(b_kr + 8) * N + n0 + b_nq);

    for (int k0 = 0; k0 < K; k0 += 16) {
        // ---- store prefetched tile to smem with big/small split ----
        {
            int ks8 = a_kq >> 3;
            int half = (a_kq >> 2) & 1;
#pragma unroll
            for (int l = 0; l < 2; ++l) {
                int row = a_row + l * 64;
                float vv[4] = {va[l].x, va[l].y, va[l].z, va[l].w};
#pragma unroll
                for (int e = 0; e < 4; ++e) {
                    uint32_t big = f2tf32(vv[e]);
                    float bf = __uint_as_float(big);
                    uint32_t sml = f2tf32(vv[e] - bf);
                    float2* dst = (float2*)&A_s[row * 9 + ks8 * 4 + e];
                    dst[half] = make_float2(__uint_as_float(big), __uint_as_float(sml));
                }
            }
#pragma unroll
            for (int l = 0; l < 2; ++l) {
                int kr = b_kr + l * 8;
                int bks8 = kr >> 3;
                int kk = kr & 7;
                int btg = kk & 3;
                int bhalf = kk >> 2;
                float vv[4] = {vb[l].x, vb[l].y, vb[l].z, vb[l].w};
#pragma unroll
                for (int e = 0; e < 4; ++e) {
                    uint32_t big = f2tf32(vv[e]);
                    float bf = __uint_as_float(big);
                    uint32_t sml = f2tf32(vv[e] - bf);
                    float2* dst = (float2*)&B_s[(b_nq + e) * 9 + bks8 * 4 + btg];
                    dst[bhalf] = make_float2(__uint_as_float(big), __uint_as_float(sml));
                }
            }
        }
        __syncthreads();

        // prefetch next tile (consumed at next iteration's store phase)
        if (k0 + 16 < K) {
            va[0] = *(const float4*)(A + (size_t)(m0 + a_row) * K + k0 + 16 + a_kq);
            va[1] = *(const float4*)(A + (size_t)(m0 + a_row + 64) * K + k0 + 16 + a_kq);
            vb[0] = *(const float4*)(B + (size_t)(k0 + 16 + b_kr) * N + n0 + b_nq);
            vb[1] = *(const float4*)(B + (size_t)(k0 + 16 + b_kr + 8) * N + n0 + b_nq);
        }

        // ---- compute: 2 k8 slices, nt in 2 chunks of 4 (reg pressure) ----
#pragma unroll
        for (int ks = 0; ks < 2; ++ks) {
            float4 p[2], q[2];
#pragma unroll
            for (int mt = 0; mt < 2; ++mt) {
                int rb = wm * 32 + mt * 16;
                p[mt] = A_s[(rb + g) * 9 + ks * 4 + tg];
                q[mt] = A_s[(rb + 8 + g) * 9 + ks * 4 + tg];
            }
#pragma unroll
            for (int nc = 0; nc < 2; ++nc) {
                float4 r[4];
#pragma unroll
                for (int j = 0; j < 4; ++j)
                    r[j] = B_s[(wn * 64 + (nc * 4 + j) * 8 + g) * 9 + ks * 4 + tg];
#pragma unroll
                for (int mt = 0; mt < 2; ++mt) {
                    uint32_t ab0 = __float_as_uint(p[mt].x), ab1 = __float_as_uint(q[mt].x);
                    uint32_t ab2 = __float_as_uint(p[mt].z), ab3 = __float_as_uint(q[mt].z);
                    uint32_t as0 = __float_as_uint(p[mt].y), as1 = __float_as_uint(q[mt].y);
                    uint32_t as2 = __float_as_uint(p[mt].w), as3 = __float_as_uint(q[mt].w);
#pragma unroll
                    for (int j = 0; j < 4; ++j) {
                        uint32_t bb0 = __float_as_uint(r[j].x), bb1 = __float_as_uint(r[j].z);
                        uint32_t bs0 = __float_as_uint(r[j].y), bs1 = __float_as_uint(r[j].w);
                        float* c = acc[mt][nc * 4 + j];
                        mma8(c, ab0, ab1, ab2, ab3, bb0, bb1);   // big x big
                        mma8(c, ab0, ab1, ab2, ab3, bs0, bs1);   // big x small
                        mma8(c, as0, as1, as2, as3, bb0, bb1);   // small x big
                    }
                }
            }
        }
        __syncthreads();
    }

    // ---- epilogue ----
#pragma unroll
    for (int mt = 0; mt < 2; ++mt) {
#pragma unroll
        for (int nt = 0; nt < 8; ++nt) {
            int row = m0 + wm * 32 + mt * 16 + g;
            int col = n0 + wn * 64 + nt * 8 + tg * 2;
            float* c = acc[mt][nt];
            *(float2*)(C + (size_t)row * N + col) = make_float2(c[0], c[1]);
            *(float2*)(C + (size_t)(row + 8) * N + col) = make_float2(c[2], c[3]);
        }
    }
}

// ---------------- reset: barrier counters + h state ------------------------
__global__ void reset_kernel() {
    int i = blockIdx.x * blockDim.x + threadIdx.x;
    if (i == 0) { g_bar_count = 0; g_bar_phase = 0; }
    if (i < 2 * HH * BB) ((float*)g_hT)[i] = 0.f;
}

// ---------------- persistent LSTM layer kernel (round-10 core, verbatim) ---
__global__ __launch_bounds__(PTH, 1) void lstm_persistent(
    const float* __restrict__ Wh,       // [HH][GN] recurrent weights
    const float* __restrict__ zx,       // [MM][GN], row = b*TT + t
    const float* __restrict__ bias,     // [GN]
    float* __restrict__ hist)           // [MM][HH] h history out
{
    extern __shared__ float smem[];
    float* w_s = smem;                           // [k*32 + col], 32768 floats
    float* h_s = smem + 32768;                   // 2 x 4096 floats
    float* z_s = smem + 32768 + 2 * 4096;        // 4 x (32*36)

    const int tid = threadIdx.x;
    const int u0 = blockIdx.x * UPB;
    const int cq = tid & 7;              // col quad: cols {4cq..4cq+3}
    const int bq = (tid >> 3) & 7;       // batch quad
    const int kq = tid >> 6;             // K quarter 0..3 (uniform per warp)
    const int gu = tid & 7;              // gate-phase unit
    const int gb = tid >> 3;             // gate-phase batch 0..31

    float* hT = (float*)g_hT;

    // ---- load weight slice into smem: w_s[k*32 + cc] ----
#pragma unroll 8
    for (int l = 0; l < 128; ++l) {
        int i = tid + l * PTH;           // 0..32767
        int k = i >> 5;
        int cc = i & 31;
        int col = ((cc >> 3) << 10) + u0 + (cc & 7);
        w_s[i] = Wh[(size_t)k * GN + col];
    }

    float bi = bias[0 * HH + u0 + gu];
    float bj = bias[1 * HH + u0 + gu];
    float bf = bias[2 * HH + u0 + gu];
    float bo = bias[3 * HH + u0 + gu];

    float creg = 0.f;
    __syncthreads();

    // per-thread chunk-load geometry: 4 float4s/thread/chunk
    const int ld_row = tid >> 3;          // base row 0..31 (stride 32)
    const int ld_c4 = (tid & 7) << 2;     // 0,4,..28

    for (int t = 0; t < TT; ++t) {
        const float* hread = hT + (t & 1) * (HH * BB);
        float* hwrite = hT + ((t + 1) & 1) * (HH * BB);

        // prefetch this step's zx for the gate phase
        const float* zxr = zx + (size_t)(gb * TT + t) * GN + u0 + gu;
        float zxi = __ldg(zxr);
        float zxj = __ldg(zxr + HH);
        float zxf = __ldg(zxr + 2 * HH);
        float zxo = __ldg(zxr + 3 * HH);

        // preload chunk 0 into buffer 0
        {
            uint32_t dst = (uint32_t)__cvta_generic_to_shared(h_s);
#pragma unroll
            for (int l = 0; l < 4; ++l) {
                int row = ld_row + l * 32;
                cp_async16(dst + (row * 32 + ld_c4) * 4,
                           hread + row * BB + ld_c4);
            }
            cp_commit();
        }

        float2 alo[4], ahi[4];
#pragma unroll
        for (int c = 0; c < 4; ++c) {
            alo[c] = make_float2(0.f, 0.f);
            ahi[c] = make_float2(0.f, 0.f);
        }

#pragma unroll 1
        for (int ch = 0; ch < 8; ++ch) {
            if (ch < 7) {   // prefetch next chunk into other buffer
                float* hb_next = h_s + ((ch + 1) & 1) * 4096;
                uint32_t dst = (uint32_t)__cvta_generic_to_shared(hb_next);
                const float* src = hread + (ch + 1) * 128 * BB;
#pragma unroll
                for (int l = 0; l < 4; ++l) {
                    int row = ld_row + l * 32;
                    cp_async16(dst + (row * 32 + ld_c4) * 4,
                               src + row * BB + ld_c4);
                }
                cp_commit();
                cp_wait<1>();
            } else {
                cp_wait<0>();
            }
            __syncthreads();   // chunk ch visible to all warps

            const float* hb = h_s + (ch & 1) * 4096 + (kq * 32) * 32 + bq * 4;
            const float* wb = w_s + (ch * 128 + kq * 32) * 32 + cq * 4;
#pragma unroll 8
            for (int kk = 0; kk < 32; ++kk) {
                float4 wv = *(const float4*)(wb + kk * 32);
                float4 hv = *(const float4*)(hb + kk * 32);
                float2 hlo = make_float2(hv.x, hv.y);
                float2 hhi = make_float2(hv.z, hv.w);
                alo[0] = ffma2(hlo, make_float2(wv.x, wv.x), alo[0]);
                ahi[0] = ffma2(hhi, make_float2(wv.x, wv.x), ahi[0]);
                alo[1] = ffma2(hlo, make_float2(wv.y, wv.y), alo[1]);
                ahi[1] = ffma2(hhi, make_float2(wv.y, wv.y), ahi[1]);
                alo[2] = ffma2(hlo, make_float2(wv.z, wv.z), alo[2]);
                ahi[2] = ffma2(hhi, make_float2(wv.z, wv.z), ahi[2]);
                alo[3] = ffma2(hlo, make_float2(wv.w, wv.w), alo[3]);
                ahi[3] = ffma2(hhi, make_float2(wv.w, wv.w), ahi[3]);
            }
            __syncthreads();   // free buffer (ch&1) for chunk ch+2 prefetch
        }

        // stage K-quarter partials to smem
        float* zh = z_s + kq * (32 * 36);
#pragma unroll
        for (int c = 0; c < 4; ++c) {
            *(float4*)(zh + (cq * 4 + c) * 36 + bq * 4) =
                make_float4(alo[c].x, alo[c].y, ahi[c].x, ahi[c].y);
        }
        __syncthreads();

        // ---- gate phase: thread = (unit gu, batch gb), combine 4 quarters --
        {
            float zi = zxi + bi, zj = zxj + bj, zf = zxf + bf, zo = zxo + bo;
#pragma unroll
            for (int q = 0; q < 4; ++q) {
                const float* zq = z_s + q * (32 * 36);
                zi += zq[(0 * 8 + gu) * 36 + gb];
                zj += zq[(1 * 8 + gu) * 36 + gb];
                zf += zq[(2 * 8 + gu) * 36 + gb];
                zo += zq[(3 * 8 + gu) * 36 + gb];
            }

            float ig = 1.f / (1.f + expf(-zi));
            float fg = 1.f / (1.f + expf(-(zf + 1.0f)));   // forget bias 1.0
            float jt = tanhf(zj);
            float cn = fg * creg + ig * jt;
            float og = 1.f / (1.f + expf(-zo));
            float hn = og * tanhf(cn);
            creg = cn;

            hwrite[(u0 + gu) * BB + gb] = hn;
            hist[(size_t)(gb * TT + t) * HH + u0 + gu] = hn;
        }

        // ---- central grid barrier, single poller per block ----
        if (t < TT - 1) {
            __syncthreads();   // block's h writes issued (also z_s guard)
            unsigned target = (unsigned)(t + 1);
            if (tid == 0) {
                unsigned prev;
                asm volatile("atom.add.release.gpu.global.u32 %0, [%1], 1;"
                             : "=r"(prev) : "l"(&g_bar_count) : "memory");
                if (prev == NBLK - 1) {
                    g_bar_count = 0;   // ordered by st.release below
                    asm volatile("st.release.gpu.global.u32 [%0], %1;"
                                 :: "l"(&g_bar_phase), "r"(target) : "memory");
                } else {
                    unsigned ph;
                    do {
                        asm volatile("ld.acquire.gpu.global.u32 %0, [%1];"
                                     : "=r"(ph) : "l"(&g_bar_phase) : "memory");
                        if (ph >= target) break;
                        __nanosleep(64);
                    } while (true);
                }
            }
            __syncthreads();
        } else {
            __syncthreads();
        }
    }
}

// ---------------- host orchestration ---------------------------------------
extern "C" void kernel_launch(void* const* d_in, const int* in_sizes, int n_in,
                              void* d_out, int out_size)
{
    const float *x = nullptr, *W1 = nullptr, *b1 = nullptr, *W2 = nullptr, *b2 = nullptr;
    for (int i = 0; i < n_in; i++) {
        int s = in_sizes[i];
        const float* p = (const float*)d_in[i];
        if (s == BB * TT * DD) x = p;
        else if (s == (DD + HH) * GN) W1 = p;
        else if (s == (HH + HH) * GN) W2 = p;
        else if (s == GN) { if (!b1) b1 = p; else b2 = p; }
    }
    float* out = (float*)d_out;

    float *zx, *h1;
    { void* p; cudaGetSymbolAddress(&p, g_zx); zx = (float*)p; }
    { void* p; cudaGetSymbolAddress(&p, g_h1); h1 = (float*)p; }

    const int SMEM_BYTES = (32768 + 2 * 4096 + 4 * 32 * 36) * 4;   // ~182 KB
    cudaFuncSetAttribute(lstm_persistent,
                         cudaFuncAttributeMaxDynamicSharedMemorySize, SMEM_BYTES);

    dim3 gemm_grid(GN / 128, MM / 128);   // (32, 64)

    // ---- Layer 1 ----
    sgemm_tf32<<<gemm_grid, 256>>>(x, W1, zx, MM, GN, DD);
    reset_kernel<<<(2 * HH * BB + 255) / 256, 256>>>();
    lstm_persistent<<<NBLK, PTH, SMEM_BYTES>>>(W1 + (size_t)DD * GN, zx, b1, h1);

    // ---- Layer 2 ----
    sgemm_tf32<<<gemm_grid, 256>>>(h1, W2, zx, MM, GN, HH);
    reset_kernel<<<(2 * HH * BB + 255) / 256, 256>>>();
    lstm_persistent<<<NBLK, PTH, SMEM_BYTES>>>(W2 + (size_t)HH * GN, zx, b2, out);
}

// round 13
// speedup vs baseline: 1.2201x; 1.1701x over previous
#include <cuda_runtime.h>
#include <cstdint>
#include <cstddef>

// Problem constants
#define BB 32
#define TT 256
#define DD 512
#define HH 1024
#define GN 4096          // 4*H gate columns
#define MM (BB*TT)       // 8192 rows

#define NBLK 128         // persistent blocks (1/SM, all co-resident)
#define UPB 8            // hidden units per block (x4 gates = 32 cols)
#define PTH 256          // threads in persistent kernel (8 warps, 2/SMSP)

// ---------------- scratch (static device allocations; no cudaMalloc) -------
__device__ float g_zx[(size_t)MM * GN];      // input-projection Z (128 MB)
__device__ float g_h1[(size_t)MM * HH];      // layer-1 hidden history (32 MB)
__device__ float g_hT[2][HH * BB];           // transposed h double buffer [unit][batch]
__device__ unsigned g_bar_count;
__device__ unsigned g_bar_phase;

// ---------------- f32x2 packed FMA (Blackwell FFMA2) -----------------------
__device__ __forceinline__ float2 ffma2(float2 a, float2 b, float2 c) {
    unsigned long long au = *reinterpret_cast<unsigned long long*>(&a);
    unsigned long long bu = *reinterpret_cast<unsigned long long*>(&b);
    unsigned long long cu = *reinterpret_cast<unsigned long long*>(&c);
    unsigned long long du;
    asm("fma.rn.f32x2 %0, %1, %2, %3;" : "=l"(du) : "l"(au), "l"(bu), "l"(cu));
    return *reinterpret_cast<float2*>(&du);
}

// ---------------- fast activations (MUFU-based, inf-safe) -------------------
__device__ __forceinline__ float sig_fast(float x) {
    return __fdividef(1.f, 1.f + __expf(-x));
}
__device__ __forceinline__ float tanh_fast(float x) {
    return __fdividef(2.f, 1.f + __expf(-2.f * x)) - 1.f;
}

// ---------------- cp.async helpers ------------------------------------------
__device__ __forceinline__ void cp_async16(uint32_t dst_smem, const void* src) {
    asm volatile("cp.async.cg.shared.global [%0], [%1], 16;" :: "r"(dst_smem), "l"(src));
}
__device__ __forceinline__ void cp_commit() {
    asm volatile("cp.async.commit_group;" ::: "memory");
}
template <int N>
__device__ __forceinline__ void cp_wait() {
    asm volatile("cp.async.wait_group %0;" :: "n"(N) : "memory");
}

// ---------------- big time-parallel GEMM: C[M,N] = A[M,K] * B[K,N] ---------
#define GM_BM 128
#define GM_BN 128
#define GM_BK 16

__global__ __launch_bounds__(256, 2) void sgemm_kernel(
    const float* __restrict__ A, const float* __restrict__ B,
    float* __restrict__ C, int M, int N, int K)
{
    __shared__ float As[GM_BK][GM_BM];
    __shared__ float Bs[GM_BK][GM_BN];

    const int tid = threadIdx.x;
    const int m0 = blockIdx.y * GM_BM;
    const int n0 = blockIdx.x * GM_BN;
    const int tx = tid & 15;
    const int ty = tid >> 4;

    float2 acc2[8][4];
#pragma unroll
    for (int i = 0; i < 8; i++)
#pragma unroll
        for (int j = 0; j < 4; j++) acc2[i][j] = make_float2(0.f, 0.f);

    for (int k0 = 0; k0 < K; k0 += GM_BK) {
#pragma unroll
        for (int l = 0; l < 2; ++l) {
            int i = tid + l * 256;
            int row = i >> 2;
            int kq = (i & 3) << 2;
            float4 v = *(const float4*)(A + (size_t)(m0 + row) * K + k0 + kq);
            As[kq + 0][row] = v.x;
            As[kq + 1][row] = v.y;
            As[kq + 2][row] = v.z;
            As[kq + 3][row] = v.w;
        }
#pragma unroll
        for (int l = 0; l < 2; ++l) {
            int i = tid + l * 256;
            int kr = i >> 5;
            int nq = (i & 31) << 2;
            *(float4*)(&Bs[kr][nq]) = *(const float4*)(B + (size_t)(k0 + kr) * N + n0 + nq);
        }
        __syncthreads();

#pragma unroll
        for (int k = 0; k < GM_BK; ++k) {
            float a[8];
            *(float4*)&a[0] = *(const float4*)&As[k][ty * 4];
            *(float4*)&a[4] = *(const float4*)&As[k][64 + ty * 4];
            float4 bv0 = *(const float4*)&Bs[k][tx * 4];
            float4 bv1 = *(const float4*)&Bs[k][64 + tx * 4];
            float2 b2[4];
            b2[0] = make_float2(bv0.x, bv0.y);
            b2[1] = make_float2(bv0.z, bv0.w);
            b2[2] = make_float2(bv1.x, bv1.y);
            b2[3] = make_float2(bv1.z, bv1.w);
#pragma unroll
            for (int i = 0; i < 8; i++) {
                float2 ad = make_float2(a[i], a[i]);
#pragma unroll
                for (int jp = 0; jp < 4; jp++)
                    acc2[i][jp] = ffma2(ad, b2[jp], acc2[i][jp]);
            }
        }
        __syncthreads();
    }

#pragma unroll
    for (int i = 0; i < 8; i++) {
        int row = m0 + ((i < 4) ? (ty * 4 + i) : (64 + ty * 4 + (i - 4)));
        float* cp = C + (size_t)row * N + n0;
        float4 v0 = make_float4(acc2[i][0].x, acc2[i][0].y, acc2[i][1].x, acc2[i][1].y);
        float4 v1 = make_float4(acc2[i][2].x, acc2[i][2].y, acc2[i][3].x, acc2[i][3].y);
        *(float4*)(cp + tx * 4) = v0;
        *(float4*)(cp + 64 + tx * 4) = v1;
    }
}

// ---------------- reset: barrier counters + h state ------------------------
__global__ void reset_kernel() {
    int i = blockIdx.x * blockDim.x + threadIdx.x;
    if (i == 0) { g_bar_count = 0; g_bar_phase = 0; }
    if (i < 2 * HH * BB) ((float*)g_hT)[i] = 0.f;
}

// ---------------- persistent LSTM layer kernel (round-10 core) -------------
// 128 blocks x 256 threads. Block bx owns units [bx*8,bx*8+8) x 4 gates (32
// cols). Thread (cq,bq,kq): cols {4cq..4cq+3} x batches {4bq..4bq+3}, K
// quarter kq. Per k: 1 LDS.128 w + 1 LDS.128 h (broadcast) -> 8 FFMA2.
// h streamed in 8 double-buffered cp.async chunks; central grid barrier.
__global__ __launch_bounds__(PTH, 1) void lstm_persistent(
    const float* __restrict__ Wh,       // [HH][GN] recurrent weights
    const float* __restrict__ zx,       // [MM][GN], row = b*TT + t
    const float* __restrict__ bias,     // [GN]
    float* __restrict__ hist)           // [MM][HH] h history out
{
    extern __shared__ float smem[];
    float* w_s = smem;                           // [k*32 + col], 32768 floats
    float* h_s = smem + 32768;                   // 2 x 4096 floats
    float* z_s = smem + 32768 + 2 * 4096;        // 4 x (32*36)

    const int tid = threadIdx.x;
    const int u0 = blockIdx.x * UPB;
    const int cq = tid & 7;              // col quad: cols {4cq..4cq+3}
    const int bq = (tid >> 3) & 7;       // batch quad
    const int kq = tid >> 6;             // K quarter 0..3 (uniform per warp)
    const int gu = tid & 7;              // gate-phase unit
    const int gb = tid >> 3;             // gate-phase batch 0..31

    float* hT = (float*)g_hT;

    // ---- load weight slice into smem: w_s[k*32 + cc] ----
#pragma unroll 8
    for (int l = 0; l < 128; ++l) {
        int i = tid + l * PTH;           // 0..32767
        int k = i >> 5;
        int cc = i & 31;
        int col = ((cc >> 3) << 10) + u0 + (cc & 7);
        w_s[i] = Wh[(size_t)k * GN + col];
    }

    float bi = bias[0 * HH + u0 + gu];
    float bj = bias[1 * HH + u0 + gu];
    float bf = bias[2 * HH + u0 + gu];
    float bo = bias[3 * HH + u0 + gu];

    float creg = 0.f;
    __syncthreads();

    // per-thread chunk-load geometry: 4 float4s/thread/chunk
    const int ld_row = tid >> 3;          // base row 0..31 (stride 32)
    const int ld_c4 = (tid & 7) << 2;     // 0,4,..28

    for (int t = 0; t < TT; ++t) {
        const float* hread = hT + (t & 1) * (HH * BB);
        float* hwrite = hT + ((t + 1) & 1) * (HH * BB);

        // prefetch this step's zx for the gate phase
        const float* zxr = zx + (size_t)(gb * TT + t) * GN + u0 + gu;
        float zxi = __ldg(zxr);
        float zxj = __ldg(zxr + HH);
        float zxf = __ldg(zxr + 2 * HH);
        float zxo = __ldg(zxr + 3 * HH);

        // preload chunk 0 into buffer 0
        {
            uint32_t dst = (uint32_t)__cvta_generic_to_shared(h_s);
#pragma unroll
            for (int l = 0; l < 4; ++l) {
                int row = ld_row + l * 32;
                cp_async16(dst + (row * 32 + ld_c4) * 4,
                           hread + row * BB + ld_c4);
            }
            cp_commit();
        }

        float2 alo[4], ahi[4];
#pragma unroll
        for (int c = 0; c < 4; ++c) {
            alo[c] = make_float2(0.f, 0.f);
            ahi[c] = make_float2(0.f, 0.f);
        }

#pragma unroll 1
        for (int ch = 0; ch < 8; ++ch) {
            if (ch < 7) {   // prefetch next chunk into other buffer
                float* hb_next = h_s + ((ch + 1) & 1) * 4096;
                uint32_t dst = (uint32_t)__cvta_generic_to_shared(hb_next);
                const float* src = hread + (ch + 1) * 128 * BB;
#pragma unroll
                for (int l = 0; l < 4; ++l) {
                    int row = ld_row + l * 32;
                    cp_async16(dst + (row * 32 + ld_c4) * 4,
                               src + row * BB + ld_c4);
                }
                cp_commit();
                cp_wait<1>();
            } else {
                cp_wait<0>();
            }
            __syncthreads();   // chunk ch visible to all warps

            const float* hb = h_s + (ch & 1) * 4096 + (kq * 32) * 32 + bq * 4;
            const float* wb = w_s + (ch * 128 + kq * 32) * 32 + cq * 4;
#pragma unroll 8
            for (int kk = 0; kk < 32; ++kk) {
                float4 wv = *(const float4*)(wb + kk * 32);
                float4 hv = *(const float4*)(hb + kk * 32);
                float2 hlo = make_float2(hv.x, hv.y);
                float2 hhi = make_float2(hv.z, hv.w);
                alo[0] = ffma2(hlo, make_float2(wv.x, wv.x), alo[0]);
                ahi[0] = ffma2(hhi, make_float2(wv.x, wv.x), ahi[0]);
                alo[1] = ffma2(hlo, make_float2(wv.y, wv.y), alo[1]);
                ahi[1] = ffma2(hhi, make_float2(wv.y, wv.y), ahi[1]);
                alo[2] = ffma2(hlo, make_float2(wv.z, wv.z), alo[2]);
                ahi[2] = ffma2(hhi, make_float2(wv.z, wv.z), ahi[2]);
                alo[3] = ffma2(hlo, make_float2(wv.w, wv.w), alo[3]);
                ahi[3] = ffma2(hhi, make_float2(wv.w, wv.w), ahi[3]);
            }
            __syncthreads();   // free buffer (ch&1) for chunk ch+2 prefetch
        }

        // stage K-quarter partials to smem
        float* zh = z_s + kq * (32 * 36);
#pragma unroll
        for (int c = 0; c < 4; ++c) {
            *(float4*)(zh + (cq * 4 + c) * 36 + bq * 4) =
                make_float4(alo[c].x, alo[c].y, ahi[c].x, ahi[c].y);
        }
        __syncthreads();

        // ---- gate phase: thread = (unit gu, batch gb), combine 4 quarters --
        {
            float zi = zxi + bi, zj = zxj + bj, zf = zxf + bf, zo = zxo + bo;
#pragma unroll
            for (int q = 0; q < 4; ++q) {
                const float* zq = z_s + q * (32 * 36);
                zi += zq[(0 * 8 + gu) * 36 + gb];
                zj += zq[(1 * 8 + gu) * 36 + gb];
                zf += zq[(2 * 8 + gu) * 36 + gb];
                zo += zq[(3 * 8 + gu) * 36 + gb];
            }

            float ig = sig_fast(zi);
            float fg = sig_fast(zf + 1.0f);    // forget bias 1.0
            float jt = tanh_fast(zj);
            float cn = fg * creg + ig * jt;
            float og = sig_fast(zo);
            float hn = og * tanh_fast(cn);
            creg = cn;

            hwrite[(u0 + gu) * BB + gb] = hn;
            hist[(size_t)(gb * TT + t) * HH + u0 + gu] = hn;
        }

        // ---- central grid barrier, single poller per block ----
        if (t < TT - 1) {
            __syncthreads();   // block's h writes issued (also z_s guard)
            unsigned target = (unsigned)(t + 1);
            if (tid == 0) {
                unsigned prev;
                asm volatile("atom.add.release.gpu.global.u32 %0, [%1], 1;"
                             : "=r"(prev) : "l"(&g_bar_count) : "memory");
                if (prev == NBLK - 1) {
                    g_bar_count = 0;   // ordered by st.release below
                    asm volatile("st.release.gpu.global.u32 [%0], %1;"
                                 :: "l"(&g_bar_phase), "r"(target) : "memory");
                } else {
                    unsigned ph;
                    do {
                        asm volatile("ld.acquire.gpu.global.u32 %0, [%1];"
                                     : "=r"(ph) : "l"(&g_bar_phase) : "memory");
                        if (ph >= target) break;
                        __nanosleep(64);
                    } while (true);
                }
            }
            __syncthreads();
        } else {
            __syncthreads();
        }
    }
}

// ---------------- host orchestration ---------------------------------------
extern "C" void kernel_launch(void* const* d_in, const int* in_sizes, int n_in,
                              void* d_out, int out_size)
{
    const float *x = nullptr, *W1 = nullptr, *b1 = nullptr, *W2 = nullptr, *b2 = nullptr;
    for (int i = 0; i < n_in; i++) {
        int s = in_sizes[i];
        const float* p = (const float*)d_in[i];
        if (s == BB * TT * DD) x = p;
        else if (s == (DD + HH) * GN) W1 = p;
        else if (s == (HH + HH) * GN) W2 = p;
        else if (s == GN) { if (!b1) b1 = p; else b2 = p; }
    }
    float* out = (float*)d_out;

    float *zx, *h1;
    { void* p; cudaGetSymbolAddress(&p, g_zx); zx = (float*)p; }
    { void* p; cudaGetSymbolAddress(&p, g_h1); h1 = (float*)p; }

    const int SMEM_BYTES = (32768 + 2 * 4096 + 4 * 32 * 36) * 4;   // ~182 KB
    cudaFuncSetAttribute(lstm_persistent,
                         cudaFuncAttributeMaxDynamicSharedMemorySize, SMEM_BYTES);

    dim3 gemm_grid(GN / GM_BN, MM / GM_BM);   // (32, 64)

    // ---- Layer 1 ----
    sgemm_kernel<<<gemm_grid, 256>>>(x, W1, zx, MM, GN, DD);
    reset_kernel<<<(2 * HH * BB + 255) / 256, 256>>>();
    // extra (idempotent) reset: shifts ncu's "-s 5 -c 1" capture window so the
    // 6th launch is lstm_persistent (recurrence profile), not sgemm.
    reset_kernel<<<(2 * HH * BB + 255) / 256, 256>>>();
    lstm_persistent<<<NBLK, PTH, SMEM_BYTES>>>(W1 + (size_t)DD * GN, zx, b1, h1);

    // ---- Layer 2 ----
    sgemm_kernel<<<gemm_grid, 256>>>(h1, W2, zx, MM, GN, HH);
    reset_kernel<<<(2 * HH * BB + 255) / 256, 256>>>();
    lstm_persistent<<<NBLK, PTH, SMEM_BYTES>>>(W2 + (size_t)HH * GN, zx, b2, out);
}